// round 14
// baseline (speedup 1.0000x reference)
#include <cuda_runtime.h>
#include <math.h>

#define Bc 8
#define Cc 64
#define Nn 128
#define Tc 288
#define TP 300
#define PRED 12
#define ROWS (Bc*Cc*Nn)   // 65536

typedef unsigned long long ull;

// ---------------- f32x2 packed helpers (FFMA2 path, sm_100+) ------------------
__device__ __forceinline__ ull packdup(float v){
    ull r; asm("mov.b64 %0, {%1, %1};" : "=l"(r) : "f"(v)); return r;
}
__device__ __forceinline__ void fma2(ull &d, ull a, ull b){
    asm("fma.rn.f32x2 %0, %1, %2, %0;" : "+l"(d) : "l"(a), "l"(b));
}
__device__ __forceinline__ ull mul2(ull a, ull b){
    ull r; asm("mul.rn.f32x2 %0, %1, %2;" : "=l"(r) : "l"(a), "l"(b));
    return r;
}
__device__ __forceinline__ void unpack2(ull v, float &lo, float &hi){
    asm("mov.b64 {%0, %1}, %2;" : "=f"(lo), "=f"(hi) : "l"(v));
}

// ---------------- scratch (static device globals; no allocation) -------------
__device__ float g_x1[ROWS*TP];
__device__ float g_x2[ROWS*TP];
__device__ float g_x3[ROWS*TP];
__device__ float g_x4[ROWS*TP];
__device__ float g_ltm[ROWS];
__device__ float g_lts[ROWS];
__device__ float g_sm[ROWS*24];
__device__ float g_ss[ROWS*24];
__device__ float g_stm[ROWS*Tc];
__device__ float g_sts[ROWS*Tc];
__device__ float g_spm[ROWS*Tc];
__device__ float g_sps[ROWS*Tc];
__device__ float g_adj[Nn*Nn];
__device__ __align__(16) float g_adjT[Nn*Nn];   // adjT[m][n] = adj[n][m]
__device__ float g_wcomb[832*2*128];   // [ic][tap][oc(128: 64 conv1 | 64 conv2)]
__device__ __align__(16) float g_wrT[64*64];    // res_w transposed [c][o]
__device__ __align__(16) float g_wkT[64*64];    // skip_w transposed [c][o]
__device__ float g_tab[Bc*Nn*24*128];  // folded const+seasonal contribution [bn][ph][oc]
__device__ float g_corr[Bc*Nn*128];    // t==0 left-pad correction [bn][oc]

// ---------------- K0: adjacency softmax -------------------------------------
__global__ void k_adj(const float* __restrict__ emb){
    int n = blockIdx.x, m = threadIdx.x;
    float d = 0.f;
    #pragma unroll
    for (int k = 0; k < 64; k++) d += emb[n*64+k]*emb[m*64+k];
    if (m == n) d -= 10.f;
    __shared__ float red[4];
    int lane = m & 31, w = m >> 5;
    float v = d;
    #pragma unroll
    for (int o = 16; o > 0; o >>= 1) v = fmaxf(v, __shfl_xor_sync(0xffffffffu, v, o));
    if (lane == 0) red[w] = v;
    __syncthreads();
    float mx = fmaxf(fmaxf(red[0],red[1]), fmaxf(red[2],red[3]));
    __syncthreads();
    float e = expf(d - mx);
    v = e;
    #pragma unroll
    for (int o = 16; o > 0; o >>= 1) v += __shfl_xor_sync(0xffffffffu, v, o);
    if (lane == 0) red[w] = v;
    __syncthreads();
    float s = red[0]+red[1]+red[2]+red[3];
    float a = e / s;
    g_adj[n*Nn + m] = a;
    g_adjT[m*Nn + n] = a;
}

// ---------------- K_w: weight reorder ----------------------------------------
__global__ void k_wprep(const float* __restrict__ c1w, const float* __restrict__ c2w,
                        const float* __restrict__ resw, const float* __restrict__ skw){
    int i = blockIdx.x*256 + threadIdx.x;
    if (i < 832*2*128) {
        int oc = i & 127, tap = (i >> 7) & 1, ic = i >> 8;
        g_wcomb[i] = (oc < 64) ? c1w[(oc*832+ic)*2 + tap]
                               : c2w[((oc-64)*832+ic)*2 + tap];
    }
    if (i < 4096) {
        int o = i >> 6, c = i & 63;
        g_wrT[c*64+o] = resw[i];
        g_wkT[c*64+o] = skw[i];
    }
}

// ---------------- K1: per-row temporal norms ---------------------------------
__global__ void k_temporal(const float* __restrict__ x){
    int row = blockIdx.x;
    int t = threadIdx.x;                       // 0..287
    __shared__ float s1[Tc], s2[Tc];
    __shared__ float rs[9], rq[9];
    __shared__ float smv[24], siv[24];
    float xv = x[row*Tc + t];
    float sum = xv, sq = xv*xv;
    #pragma unroll
    for (int o = 16; o > 0; o >>= 1) {
        sum += __shfl_down_sync(0xffffffffu, sum, o);
        sq  += __shfl_down_sync(0xffffffffu, sq,  o);
    }
    if ((t & 31) == 0) { rs[t>>5] = sum; rq[t>>5] = sq; }
    __syncthreads();
    if (t == 0) {
        float a = 0.f, b = 0.f;
        #pragma unroll
        for (int i = 0; i < 9; i++) { a += rs[i]; b += rq[i]; }
        rs[0] = a; rq[0] = b;
    }
    __syncthreads();
    float m1 = rs[0] * (1.f/Tc);
    float v1 = rq[0] * (1.f/Tc) - m1*m1 + 1e-5f;
    float x1v = (xv - m1) * rsqrtf(v1 + 0.01f);
    s1[t] = x1v;
    g_x1[row*TP + t] = x1v;
    if (t == 0) { g_ltm[row] = m1; g_lts[row] = sqrtf(v1); }
    __syncthreads();
    if (t < 24) {
        float a = 0.f, b = 0.f;
        #pragma unroll
        for (int k = 0; k < 12; k++) { float v = s1[t + 24*k]; a += v; b += v*v; }
        float mm = a * (1.f/12.f);
        float vv = b * (1.f/12.f) - mm*mm + 1e-5f;
        smv[t] = mm;
        siv[t] = rsqrtf(vv + 0.01f);
        g_sm[row*24 + t] = mm;
        g_ss[row*24 + t] = sqrtf(vv);
    }
    __syncthreads();
    int ph = t % 24;
    float x2v = (x1v - smv[ph]) * siv[ph];
    s2[t] = x2v;
    g_x2[row*TP + t] = x2v;
    __syncthreads();
    int te = (t < 11) ? 11 : t;
    float a = 0.f, b = 0.f;
    #pragma unroll
    for (int j = 0; j < 12; j++) { float v = s2[te-11+j]; a += v; b += v*v; }
    float mm = a * (1.f/12.f);
    float vv = b * (1.f/12.f) - mm*mm + 1e-5f;
    g_stm[row*Tc + t] = mm;
    g_sts[row*Tc + t] = sqrtf(vv);
    g_x3[row*TP + t] = (x2v - mm) * rsqrtf(vv + 0.01f);
}

// ---------------- K2: spatial norm (register-tiled, f32x2) --------------------
__global__ void __launch_bounds__(256) k_spatial(){
    int bc = blockIdx.x;            // 0..511 (b*64+c)
    int t0 = blockIdx.y * 32;
    __shared__ __align__(16) float s3[Nn*32];   // [m][t] 16KB
    int tid = threadIdx.x;          // 256
    for (int idx = tid; idx < Nn*32; idx += 256) {
        int m = idx >> 5, j = idx & 31;
        s3[idx] = g_x3[(bc*Nn + m)*TP + t0 + j];
    }
    __syncthreads();
    int tx = tid & 7, ty = tid >> 3;   // 8 t-groups x 32 n-groups
    int tb = tx*4, n0 = ty*4;
    ull a1p[2][4] = {}, a2p[2][4] = {};
    #pragma unroll 4
    for (int m = 0; m < Nn; m++) {
        float4 xv = *(const float4*)&s3[m*32 + tb];
        ulonglong2 ap = *(const ulonglong2*)&g_adjT[m*Nn + n0];
        ull xd[4] = {packdup(xv.x), packdup(xv.y), packdup(xv.z), packdup(xv.w)};
        #pragma unroll
        for (int j = 0; j < 4; j++) {
            ull xq = mul2(xd[j], xd[j]);
            fma2(a1p[0][j], ap.x, xd[j]);
            fma2(a1p[1][j], ap.y, xd[j]);
            fma2(a2p[0][j], ap.x, xq);
            fma2(a2p[1][j], ap.y, xq);
        }
    }
    #pragma unroll
    for (int ip = 0; ip < 2; ip++) {
        float mn[2][4], sq[2][4];
        #pragma unroll
        for (int j = 0; j < 4; j++) {
            unpack2(a1p[ip][j], mn[0][j], mn[1][j]);
            unpack2(a2p[ip][j], sq[0][j], sq[1][j]);
        }
        #pragma unroll
        for (int h = 0; h < 2; h++) {
            int n = n0 + ip*2 + h;
            int ro = bc*Nn + n;
            float x4o[4], mo[4], so[4];
            #pragma unroll
            for (int j = 0; j < 4; j++) {
                float mean = mn[h][j];
                float var = sq[h][j] - mean*mean + 1e-5f;
                float xv = s3[n*32 + tb + j];
                x4o[j] = (xv - mean) * rsqrtf(var + 0.01f);
                mo[j] = mean;
                so[j] = sqrtf(var);
            }
            *(float4*)&g_x4[ro*TP + t0 + tb]  = *(float4*)x4o;
            *(float4*)&g_spm[ro*Tc + t0 + tb] = *(float4*)mo;
            *(float4*)&g_sps[ro*Tc + t0 + tb] = *(float4*)so;
        }
    }
}

// ---------------- K3: residual extrapolation GEMMs ---------------------------
__global__ void __launch_bounds__(256) k_extrap(
        const float* __restrict__ w1, const float* __restrict__ b1,
        const float* __restrict__ w2, const float* __restrict__ b2,
        const float* __restrict__ w3, const float* __restrict__ b3,
        const float* __restrict__ w4, const float* __restrict__ b4){
    int which = blockIdx.z >> 3;
    int b = blockIdx.z & 7;
    int o0 = blockIdx.x * 64;
    int n0 = blockIdx.y * 32;
    const float* wt; const float* bs; float* xio;
    if (which == 0)      { wt = w1; bs = b1; xio = g_x1; }
    else if (which == 1) { wt = w2; bs = b2; xio = g_x2; }
    else if (which == 2) { wt = w3; bs = b3; xio = g_x3; }
    else                 { wt = w4; bs = b4; xio = g_x4; }

    __shared__ __align__(16) float Vs[64*32];
    __shared__ float Ws[64*64];
    int tid = threadIdx.x;
    int tx = tid & 7;          // 4 n each
    int ty = tid >> 3;         // o = o0+ty and o0+ty+32
    float acc0[4] = {0,0,0,0}, acc1[4] = {0,0,0,0};
    for (int kt = 0; kt < 12; kt++) {
        __syncthreads();
        for (int idx = tid; idx < 2048; idx += 256) {
            int k = idx >> 5, nn = idx & 31;
            int kk = kt*64 + k;
            int c = kk / 12, l = kk - c*12;
            Vs[idx] = xio[((b*Cc + c)*Nn + n0 + nn)*TP + 276 + l];
        }
        for (int idx = tid; idx < 4096; idx += 256) {
            int k = idx >> 6, oc = idx & 63;
            Ws[idx] = wt[(o0 + oc)*768 + kt*64 + k];
        }
        __syncthreads();
        #pragma unroll 8
        for (int k = 0; k < 64; k++) {
            float w0 = Ws[k*64 + ty];
            float wA = Ws[k*64 + 32 + ty];
            float4 vv = *(const float4*)&Vs[k*32 + tx*4];
            float v[4] = {vv.x, vv.y, vv.z, vv.w};
            #pragma unroll
            for (int j = 0; j < 4; j++) {
                acc0[j] = fmaf(w0, v[j], acc0[j]);
                acc1[j] = fmaf(wA, v[j], acc1[j]);
            }
        }
    }
    int o = o0 + ty;
    float bv = bs[o];
    int p = o >> 6, c2 = o & 63;
    #pragma unroll
    for (int j = 0; j < 4; j++)
        xio[((b*Cc + c2)*Nn + n0 + tx*4 + j)*TP + Tc + p] = acc0[j] + bv;
    o = o0 + ty + 32;
    bv = bs[o]; p = o >> 6; c2 = o & 63;
    #pragma unroll
    for (int j = 0; j < 4; j++)
        xio[((b*Cc + c2)*Nn + n0 + tx*4 + j)*TP + Tc + p] = acc1[j] + bv;
}

// ---------------- K_tab: fold constant + periodic xcat groups ----------------
__global__ void __launch_bounds__(128) k_tab(){
    int bn = blockIdx.x;            // b*128 + n
    int b = bn >> 7, n = bn & 127;
    __shared__ float s_sm[64*24], s_ss[64*24], s_ltm[64], s_lts[64];
    int tid = threadIdx.x;
    for (int idx = tid; idx < 1536; idx += 128) {
        int c = idx / 24, ph = idx - c*24;
        int row = (b*Cc + c)*Nn + n;
        s_sm[idx] = g_sm[row*24 + ph];
        s_ss[idx] = g_ss[row*24 + ph];
    }
    if (tid < 64) {
        int row = (b*Cc + tid)*Nn + n;
        s_ltm[tid] = g_ltm[row];
        s_lts[tid] = g_lts[row];
    }
    __syncthreads();
    int oc = tid;                   // 0..127
    float tab[24];
    #pragma unroll
    for (int p = 0; p < 24; p++) tab[p] = 0.f;
    float corr = 0.f, base = 0.f;
    for (int c = 0; c < 64; c++) {
        float w2t0 = g_wcomb[((128+c)*2+0)*128+oc];
        float w2t1 = g_wcomb[((128+c)*2+1)*128+oc];
        float w3t0 = g_wcomb[((192+c)*2+0)*128+oc];
        float w3t1 = g_wcomb[((192+c)*2+1)*128+oc];
        base += (w2t0+w2t1)*s_ltm[c] + (w3t0+w3t1)*s_lts[c];
        corr += w2t0*s_ltm[c] + w3t0*s_lts[c];
        float w5t0 = g_wcomb[((320+c)*2+0)*128+oc];
        float w5t1 = g_wcomb[((320+c)*2+1)*128+oc];
        float w6t0 = g_wcomb[((384+c)*2+0)*128+oc];
        float w6t1 = g_wcomb[((384+c)*2+1)*128+oc];
        const float* smc = &s_sm[c*24];
        const float* ssc = &s_ss[c*24];
        corr += w5t0*smc[23] + w6t0*ssc[23];
        #pragma unroll
        for (int p = 0; p < 24; p++) {
            int pm = (p + 23) % 24;   // phase of t-1
            tab[p] = fmaf(w5t0, smc[pm], tab[p]);
            tab[p] = fmaf(w5t1, smc[p],  tab[p]);
            tab[p] = fmaf(w6t0, ssc[pm], tab[p]);
            tab[p] = fmaf(w6t1, ssc[p],  tab[p]);
        }
    }
    #pragma unroll
    for (int p = 0; p < 24; p++)
        g_tab[(bn*24 + p)*128 + oc] = tab[p] + base;
    g_corr[bn*128 + oc] = corr;
}

// ---------------- K4: fused gated conv + output 1x1s (f32x2, 2 nodes) --------
__device__ __forceinline__ float gather_xcat(const float* __restrict__ x,
                                             int b, int ch, int n, int t){
    int g = ch >> 6, c = ch & 63;
    int row = (b*Cc + c)*Nn + n;
    int tc = (t < Tc) ? t : (Tc - 1);
    switch (g) {
        case 0:  return x[row*Tc + tc];
        case 1:  return g_x1[row*TP + t];
        case 4:  return g_x2[row*TP + t];
        case 7:  return g_x3[row*TP + t];
        case 8:  return g_stm[row*Tc + tc];
        case 9:  return g_sts[row*Tc + tc];
        case 10: return g_x4[row*TP + t];
        case 11: return g_spm[row*Tc + tc];
        default: return g_sps[row*Tc + tc];   // 12
    }
}

// dynamic smem layout (floats):
//   xs    [0, 2176)            2 nodes x 16 ic x 68
//   sw    [2176, 10880)        weights (4096 used) in loop; z [2][64][68] after
//   tabs  [10880, 17024)       2 x 3072
//   corrs [17024, 17280)       2 x 128
#define SM_XS    0
#define SM_SW    2176
#define SM_TABS  10880
#define SM_CORRS 17024
#define SMEM_FLOATS 17280
#define SMEM_BYTES (SMEM_FLOATS*4)

__global__ void __launch_bounds__(256, 1) k_convout(const float* __restrict__ x,
        const float* __restrict__ c1b, const float* __restrict__ c2b,
        const float* __restrict__ resb, const float* __restrict__ skb,
        float* __restrict__ out){
    extern __shared__ __align__(16) float sm[];
    float* xs    = sm + SM_XS;
    float* sw    = sm + SM_SW;
    float* tabs  = sm + SM_TABS;
    float* corrs = sm + SM_CORRS;

    int t0 = blockIdx.x * 64;
    int n0 = blockIdx.y * 2;
    int b  = blockIdx.z;
    int bn0 = b*Nn + n0;
    int tid = threadIdx.x;
    for (int idx = tid; idx < 6144; idx += 256) tabs[idx] = g_tab[bn0*3072 + idx];
    if (tid < 256) { }   // (all threads used below)
    for (int idx = tid; idx < 256; idx += 256) corrs[idx] = g_corr[bn0*128 + idx];

    int ocg = tid & 15;   // c base = ocg*4
    int tg  = tid >> 4;   // t base = tg*4
    int tb4 = tg*4;
    ull acc1[2][2][4] = {}, acc2[2][2][4] = {};   // [node][oc-pair][t]
    for (int kti = 0; kti < 36; kti++) {
        // skip kt in {8..15} (const groups 2,3) and {20..27} (seasonal 5,6)
        int kt = (kti < 8) ? kti : ((kti < 12) ? kti + 8 : kti + 16);
        __syncthreads();
        for (int idx = tid; idx < 2*16*65; idx += 256) {
            int nn = (idx >= 1040) ? 1 : 0;
            int r = idx - nn*1040;
            int icl = r / 65, j = r - icl*65;
            int t = t0 - 1 + j;
            float v = 0.f;
            if (t >= 0 && t < TP) v = gather_xcat(x, b, kt*16 + icl, n0 + nn, t);
            xs[nn*1088 + icl*68 + j] = v;
        }
        for (int idx = tid; idx < 4096; idx += 256)
            sw[idx] = g_wcomb[kt*4096 + idx];
        __syncthreads();
        #pragma unroll
        for (int ic = 0; ic < 16; ic++) {
            const float* x0 = &xs[ic*68 + tb4];
            const float* x1 = &xs[1088 + ic*68 + tb4];
            float4 a0 = *(const float4*)x0; float e0 = x0[4];
            float4 a1 = *(const float4*)x1; float e1 = x1[4];
            ull xd0[5] = {packdup(a0.x), packdup(a0.y), packdup(a0.z),
                          packdup(a0.w), packdup(e0)};
            ull xd1[5] = {packdup(a1.x), packdup(a1.y), packdup(a1.z),
                          packdup(a1.w), packdup(e1)};
            #pragma unroll
            for (int tap = 0; tap < 2; tap++) {
                ulonglong2 wA = *(const ulonglong2*)&sw[(ic*2+tap)*128 + ocg*4];
                ulonglong2 wB = *(const ulonglong2*)&sw[(ic*2+tap)*128 + 64 + ocg*4];
                #pragma unroll
                for (int j = 0; j < 4; j++) {
                    fma2(acc1[0][0][j], wA.x, xd0[j+tap]);
                    fma2(acc1[0][1][j], wA.y, xd0[j+tap]);
                    fma2(acc2[0][0][j], wB.x, xd0[j+tap]);
                    fma2(acc2[0][1][j], wB.y, xd0[j+tap]);
                    fma2(acc1[1][0][j], wA.x, xd1[j+tap]);
                    fma2(acc1[1][1][j], wA.y, xd1[j+tap]);
                    fma2(acc2[1][0][j], wB.x, xd1[j+tap]);
                    fma2(acc2[1][1][j], wB.y, xd1[j+tap]);
                }
            }
        }
    }
    __syncthreads();   // done reading sw as weights
    // gating epilogue: z -> sw[nn*4352 + c*68 + lt]
    #pragma unroll
    for (int nn = 0; nn < 2; nn++) {
        float f1[4][4], f2[4][4];
        #pragma unroll
        for (int ip = 0; ip < 2; ip++)
            #pragma unroll
            for (int j = 0; j < 4; j++) {
                unpack2(acc1[nn][ip][j], f1[ip*2][j], f1[ip*2+1][j]);
                unpack2(acc2[nn][ip][j], f2[ip*2][j], f2[ip*2+1][j]);
            }
        #pragma unroll
        for (int i = 0; i < 4; i++) {
            int c = ocg*4 + i;
            float bb1 = c1b[c], bb2 = c2b[c];
            #pragma unroll
            for (int j = 0; j < 4; j++) {
                int lt = tb4 + j;
                int t = t0 + lt;
                int ph = t % 24;
                float a1v = f1[i][j] + tabs[nn*3072 + ph*128 + c]      + bb1;
                float a2v = f2[i][j] + tabs[nn*3072 + ph*128 + 64 + c] + bb2;
                if (t == 0) { a1v -= corrs[nn*128 + c]; a2v -= corrs[nn*128 + 64 + c]; }
                float zg = tanhf(a1v) * (1.f / (1.f + expf(-a2v)));
                sw[nn*4352 + c*68 + lt] = zg;
            }
        }
    }
    __syncthreads();
    // output 1x1 convs on z (f32x2), both nodes
    const float* wsel = (t0 + tb4 >= Tc) ? g_wkT : g_wrT;
    ull ao[2][2][4] = {};
    #pragma unroll 4
    for (int k = 0; k < 64; k++) {
        ulonglong2 wp = *(const ulonglong2*)&wsel[k*64 + ocg*4];
        float4 zv0 = *(const float4*)&sw[k*68 + tb4];
        float4 zv1 = *(const float4*)&sw[4352 + k*68 + tb4];
        ull zd0[4] = {packdup(zv0.x), packdup(zv0.y), packdup(zv0.z), packdup(zv0.w)};
        ull zd1[4] = {packdup(zv1.x), packdup(zv1.y), packdup(zv1.z), packdup(zv1.w)};
        #pragma unroll
        for (int j = 0; j < 4; j++) {
            fma2(ao[0][0][j], wp.x, zd0[j]);
            fma2(ao[0][1][j], wp.y, zd0[j]);
            fma2(ao[1][0][j], wp.x, zd1[j]);
            fma2(ao[1][1][j], wp.y, zd1[j]);
        }
    }
    const size_t SZ1 = (size_t)Bc*Cc*Nn*Tc;
    #pragma unroll
    for (int nn = 0; nn < 2; nn++) {
        int n = n0 + nn;
        float acc[4][4];
        #pragma unroll
        for (int ip = 0; ip < 2; ip++)
            #pragma unroll
            for (int j = 0; j < 4; j++)
                unpack2(ao[nn][ip][j], acc[ip*2][j], acc[ip*2+1][j]);
        #pragma unroll
        for (int i = 0; i < 4; i++) {
            int oc = ocg*4 + i;
            float br = resb[oc], bk = skb[oc];
            #pragma unroll
            for (int j = 0; j < 4; j++) {
                int t = t0 + tb4 + j;
                if (t < Tc)
                    out[((size_t)(b*Cc + oc)*Nn + n)*Tc + t] = acc[i][j] + br;
                else if (t < TP)
                    out[SZ1 + ((size_t)(b*Cc + oc)*Nn + n)*PRED + (t - Tc)] = acc[i][j] + bk;
            }
        }
    }
}

// ---------------- launcher ----------------------------------------------------
extern "C" void kernel_launch(void* const* d_in, const int* in_sizes, int n_in,
                              void* d_out, int out_size){
    const float* x    = (const float*)d_in[0];
    const float* emb  = (const float*)d_in[1];
    const float* re1w = (const float*)d_in[2];  const float* re1b = (const float*)d_in[3];
    const float* re2w = (const float*)d_in[4];  const float* re2b = (const float*)d_in[5];
    const float* re3w = (const float*)d_in[6];  const float* re3b = (const float*)d_in[7];
    const float* re4w = (const float*)d_in[8];  const float* re4b = (const float*)d_in[9];
    const float* c1w  = (const float*)d_in[10]; const float* c1b  = (const float*)d_in[11];
    const float* c2w  = (const float*)d_in[12]; const float* c2b  = (const float*)d_in[13];
    const float* skw  = (const float*)d_in[14]; const float* skb  = (const float*)d_in[15];
    const float* resw = (const float*)d_in[16]; const float* resb = (const float*)d_in[17];

    cudaFuncSetAttribute(k_convout, cudaFuncAttributeMaxDynamicSharedMemorySize,
                         SMEM_BYTES);

    k_adj<<<128, 128>>>(emb);
    k_wprep<<<(832*2*128 + 255)/256, 256>>>(c1w, c2w, resw, skw);
    k_temporal<<<ROWS, Tc>>>(x);
    k_spatial<<<dim3(512, 9, 1), 256>>>();
    k_extrap<<<dim3(12, 4, 32), 256>>>(re1w, re1b, re2w, re2b, re3w, re3b, re4w, re4b);
    k_tab<<<Bc*Nn, 128>>>();
    k_convout<<<dim3(5, 64, 8), 256, SMEM_BYTES>>>(x, c1b, c2b, resb, skb, (float*)d_out);
}

// round 16
// speedup vs baseline: 1.3204x; 1.3204x over previous
#include <cuda_runtime.h>
#include <math.h>

#define Bc 8
#define Cc 64
#define Nn 128
#define Tc 288
#define TP 300
#define PRED 12
#define ROWS (Bc*Cc*Nn)   // 65536

typedef unsigned long long ull;

// ---------------- f32x2 packed helpers (FFMA2 path, sm_100+) ------------------
__device__ __forceinline__ ull packdup(float v){
    ull r; asm("mov.b64 %0, {%1, %1};" : "=l"(r) : "f"(v)); return r;
}
__device__ __forceinline__ void fma2(ull &d, ull a, ull b){
    asm("fma.rn.f32x2 %0, %1, %2, %0;" : "+l"(d) : "l"(a), "l"(b));
}
__device__ __forceinline__ ull mul2(ull a, ull b){
    ull r; asm("mul.rn.f32x2 %0, %1, %2;" : "=l"(r) : "l"(a), "l"(b));
    return r;
}
__device__ __forceinline__ void unpack2(ull v, float &lo, float &hi){
    asm("mov.b64 {%0, %1}, %2;" : "=f"(lo), "=f"(hi) : "l"(v));
}

// ---------------- scratch (static device globals; no allocation) -------------
__device__ float g_x1[ROWS*TP];
__device__ float g_x2[ROWS*TP];
__device__ float g_x3[ROWS*TP];
__device__ float g_x4[ROWS*TP];
__device__ float g_ltm[ROWS];
__device__ float g_lts[ROWS];
__device__ float g_sm[ROWS*24];
__device__ float g_ss[ROWS*24];
__device__ float g_stm[ROWS*Tc];
__device__ float g_sts[ROWS*Tc];
__device__ float g_spm[ROWS*Tc];
__device__ float g_sps[ROWS*Tc];
__device__ float g_adj[Nn*Nn];
__device__ __align__(16) float g_adjT[Nn*Nn];   // adjT[m][n] = adj[n][m]
__device__ __align__(16) float g_wcomb[832*2*128]; // [ic][tap][oc(128)]
__device__ __align__(16) float g_wrT[64*64];    // res_w transposed [c][o]
__device__ __align__(16) float g_wkT[64*64];    // skip_w transposed [c][o]
__device__ float g_tab[Bc*Nn*24*128];  // folded const+seasonal contribution [bn][ph][oc]
__device__ float g_corr[Bc*Nn*128];    // t==0 left-pad correction [bn][oc]

// ---------------- K0: adjacency softmax -------------------------------------
__global__ void k_adj(const float* __restrict__ emb){
    int n = blockIdx.x, m = threadIdx.x;
    float d = 0.f;
    #pragma unroll
    for (int k = 0; k < 64; k++) d += emb[n*64+k]*emb[m*64+k];
    if (m == n) d -= 10.f;
    __shared__ float red[4];
    int lane = m & 31, w = m >> 5;
    float v = d;
    #pragma unroll
    for (int o = 16; o > 0; o >>= 1) v = fmaxf(v, __shfl_xor_sync(0xffffffffu, v, o));
    if (lane == 0) red[w] = v;
    __syncthreads();
    float mx = fmaxf(fmaxf(red[0],red[1]), fmaxf(red[2],red[3]));
    __syncthreads();
    float e = expf(d - mx);
    v = e;
    #pragma unroll
    for (int o = 16; o > 0; o >>= 1) v += __shfl_xor_sync(0xffffffffu, v, o);
    if (lane == 0) red[w] = v;
    __syncthreads();
    float s = red[0]+red[1]+red[2]+red[3];
    float a = e / s;
    g_adj[n*Nn + m] = a;
    g_adjT[m*Nn + n] = a;
}

// ---------------- K_w: weight reorder ----------------------------------------
__global__ void k_wprep(const float* __restrict__ c1w, const float* __restrict__ c2w,
                        const float* __restrict__ resw, const float* __restrict__ skw){
    int i = blockIdx.x*256 + threadIdx.x;
    if (i < 832*2*128) {
        int oc = i & 127, tap = (i >> 7) & 1, ic = i >> 8;
        g_wcomb[i] = (oc < 64) ? c1w[(oc*832+ic)*2 + tap]
                               : c2w[((oc-64)*832+ic)*2 + tap];
    }
    if (i < 4096) {
        int o = i >> 6, c = i & 63;
        g_wrT[c*64+o] = resw[i];
        g_wkT[c*64+o] = skw[i];
    }
}

// ---------------- K1: per-row temporal norms ---------------------------------
__global__ void k_temporal(const float* __restrict__ x){
    int row = blockIdx.x;
    int t = threadIdx.x;                       // 0..287
    __shared__ float s1[Tc], s2[Tc];
    __shared__ float rs[9], rq[9];
    __shared__ float smv[24], siv[24];
    float xv = x[row*Tc + t];
    float sum = xv, sq = xv*xv;
    #pragma unroll
    for (int o = 16; o > 0; o >>= 1) {
        sum += __shfl_down_sync(0xffffffffu, sum, o);
        sq  += __shfl_down_sync(0xffffffffu, sq,  o);
    }
    if ((t & 31) == 0) { rs[t>>5] = sum; rq[t>>5] = sq; }
    __syncthreads();
    if (t == 0) {
        float a = 0.f, b = 0.f;
        #pragma unroll
        for (int i = 0; i < 9; i++) { a += rs[i]; b += rq[i]; }
        rs[0] = a; rq[0] = b;
    }
    __syncthreads();
    float m1 = rs[0] * (1.f/Tc);
    float v1 = rq[0] * (1.f/Tc) - m1*m1 + 1e-5f;
    float x1v = (xv - m1) * rsqrtf(v1 + 0.01f);
    s1[t] = x1v;
    g_x1[row*TP + t] = x1v;
    if (t == 0) { g_ltm[row] = m1; g_lts[row] = sqrtf(v1); }
    __syncthreads();
    if (t < 24) {
        float a = 0.f, b = 0.f;
        #pragma unroll
        for (int k = 0; k < 12; k++) { float v = s1[t + 24*k]; a += v; b += v*v; }
        float mm = a * (1.f/12.f);
        float vv = b * (1.f/12.f) - mm*mm + 1e-5f;
        smv[t] = mm;
        siv[t] = rsqrtf(vv + 0.01f);
        g_sm[row*24 + t] = mm;
        g_ss[row*24 + t] = sqrtf(vv);
    }
    __syncthreads();
    int ph = t % 24;
    float x2v = (x1v - smv[ph]) * siv[ph];
    s2[t] = x2v;
    g_x2[row*TP + t] = x2v;
    __syncthreads();
    int te = (t < 11) ? 11 : t;
    float a = 0.f, b = 0.f;
    #pragma unroll
    for (int j = 0; j < 12; j++) { float v = s2[te-11+j]; a += v; b += v*v; }
    float mm = a * (1.f/12.f);
    float vv = b * (1.f/12.f) - mm*mm + 1e-5f;
    g_stm[row*Tc + t] = mm;
    g_sts[row*Tc + t] = sqrtf(vv);
    g_x3[row*TP + t] = (x2v - mm) * rsqrtf(vv + 0.01f);
}

// ---------------- K2: spatial norm (register-tiled, f32x2) --------------------
__global__ void __launch_bounds__(256) k_spatial(){
    int bc = blockIdx.x;            // 0..511 (b*64+c)
    int t0 = blockIdx.y * 32;
    __shared__ __align__(16) float s3[Nn*32];   // [m][t] 16KB
    int tid = threadIdx.x;          // 256
    for (int idx = tid; idx < Nn*32; idx += 256) {
        int m = idx >> 5, j = idx & 31;
        s3[idx] = g_x3[(bc*Nn + m)*TP + t0 + j];
    }
    __syncthreads();
    int tx = tid & 7, ty = tid >> 3;   // 8 t-groups x 32 n-groups
    int tb = tx*4, n0 = ty*4;
    ull a1p[2][4] = {}, a2p[2][4] = {};
    #pragma unroll 4
    for (int m = 0; m < Nn; m++) {
        float4 xv = *(const float4*)&s3[m*32 + tb];
        ulonglong2 ap = *(const ulonglong2*)&g_adjT[m*Nn + n0];
        ull xd[4] = {packdup(xv.x), packdup(xv.y), packdup(xv.z), packdup(xv.w)};
        #pragma unroll
        for (int j = 0; j < 4; j++) {
            ull xq = mul2(xd[j], xd[j]);
            fma2(a1p[0][j], ap.x, xd[j]);
            fma2(a1p[1][j], ap.y, xd[j]);
            fma2(a2p[0][j], ap.x, xq);
            fma2(a2p[1][j], ap.y, xq);
        }
    }
    #pragma unroll
    for (int ip = 0; ip < 2; ip++) {
        float mn[2][4], sq[2][4];
        #pragma unroll
        for (int j = 0; j < 4; j++) {
            unpack2(a1p[ip][j], mn[0][j], mn[1][j]);
            unpack2(a2p[ip][j], sq[0][j], sq[1][j]);
        }
        #pragma unroll
        for (int h = 0; h < 2; h++) {
            int n = n0 + ip*2 + h;
            int ro = bc*Nn + n;
            float x4o[4], mo[4], so[4];
            #pragma unroll
            for (int j = 0; j < 4; j++) {
                float mean = mn[h][j];
                float var = sq[h][j] - mean*mean + 1e-5f;
                float xv = s3[n*32 + tb + j];
                x4o[j] = (xv - mean) * rsqrtf(var + 0.01f);
                mo[j] = mean;
                so[j] = sqrtf(var);
            }
            *(float4*)&g_x4[ro*TP + t0 + tb]  = *(float4*)x4o;
            *(float4*)&g_spm[ro*Tc + t0 + tb] = *(float4*)mo;
            *(float4*)&g_sps[ro*Tc + t0 + tb] = *(float4*)so;
        }
    }
}

// ---------------- K3: residual extrapolation GEMMs ---------------------------
__global__ void __launch_bounds__(256) k_extrap(
        const float* __restrict__ w1, const float* __restrict__ b1,
        const float* __restrict__ w2, const float* __restrict__ b2,
        const float* __restrict__ w3, const float* __restrict__ b3,
        const float* __restrict__ w4, const float* __restrict__ b4){
    int which = blockIdx.z >> 3;
    int b = blockIdx.z & 7;
    int o0 = blockIdx.x * 64;
    int n0 = blockIdx.y * 32;
    const float* wt; const float* bs; float* xio;
    if (which == 0)      { wt = w1; bs = b1; xio = g_x1; }
    else if (which == 1) { wt = w2; bs = b2; xio = g_x2; }
    else if (which == 2) { wt = w3; bs = b3; xio = g_x3; }
    else                 { wt = w4; bs = b4; xio = g_x4; }

    __shared__ __align__(16) float Vs[64*32];
    __shared__ float Ws[64*64];
    int tid = threadIdx.x;
    int tx = tid & 7;          // 4 n each
    int ty = tid >> 3;         // o = o0+ty and o0+ty+32
    float acc0[4] = {0,0,0,0}, acc1[4] = {0,0,0,0};
    for (int kt = 0; kt < 12; kt++) {
        __syncthreads();
        for (int idx = tid; idx < 2048; idx += 256) {
            int k = idx >> 5, nn = idx & 31;
            int kk = kt*64 + k;
            int c = kk / 12, l = kk - c*12;
            Vs[idx] = xio[((b*Cc + c)*Nn + n0 + nn)*TP + 276 + l];
        }
        for (int idx = tid; idx < 4096; idx += 256) {
            int k = idx >> 6, oc = idx & 63;
            Ws[idx] = wt[(o0 + oc)*768 + kt*64 + k];
        }
        __syncthreads();
        #pragma unroll 8
        for (int k = 0; k < 64; k++) {
            float w0 = Ws[k*64 + ty];
            float wA = Ws[k*64 + 32 + ty];
            float4 vv = *(const float4*)&Vs[k*32 + tx*4];
            float v[4] = {vv.x, vv.y, vv.z, vv.w};
            #pragma unroll
            for (int j = 0; j < 4; j++) {
                acc0[j] = fmaf(w0, v[j], acc0[j]);
                acc1[j] = fmaf(wA, v[j], acc1[j]);
            }
        }
    }
    int o = o0 + ty;
    float bv = bs[o];
    int p = o >> 6, c2 = o & 63;
    #pragma unroll
    for (int j = 0; j < 4; j++)
        xio[((b*Cc + c2)*Nn + n0 + tx*4 + j)*TP + Tc + p] = acc0[j] + bv;
    o = o0 + ty + 32;
    bv = bs[o]; p = o >> 6; c2 = o & 63;
    #pragma unroll
    for (int j = 0; j < 4; j++)
        xio[((b*Cc + c2)*Nn + n0 + tx*4 + j)*TP + Tc + p] = acc1[j] + bv;
}

// ---------------- K_tab: fold constant + periodic xcat groups ----------------
__global__ void __launch_bounds__(128) k_tab(){
    int bn = blockIdx.x;            // b*128 + n
    int b = bn >> 7, n = bn & 127;
    __shared__ float s_sm[64*24], s_ss[64*24], s_ltm[64], s_lts[64];
    int tid = threadIdx.x;
    for (int idx = tid; idx < 1536; idx += 128) {
        int c = idx / 24, ph = idx - c*24;
        int row = (b*Cc + c)*Nn + n;
        s_sm[idx] = g_sm[row*24 + ph];
        s_ss[idx] = g_ss[row*24 + ph];
    }
    if (tid < 64) {
        int row = (b*Cc + tid)*Nn + n;
        s_ltm[tid] = g_ltm[row];
        s_lts[tid] = g_lts[row];
    }
    __syncthreads();
    int oc = tid;                   // 0..127
    float tab[24];
    #pragma unroll
    for (int p = 0; p < 24; p++) tab[p] = 0.f;
    float corr = 0.f, base = 0.f;
    for (int c = 0; c < 64; c++) {
        float w2t0 = g_wcomb[((128+c)*2+0)*128+oc];
        float w2t1 = g_wcomb[((128+c)*2+1)*128+oc];
        float w3t0 = g_wcomb[((192+c)*2+0)*128+oc];
        float w3t1 = g_wcomb[((192+c)*2+1)*128+oc];
        base += (w2t0+w2t1)*s_ltm[c] + (w3t0+w3t1)*s_lts[c];
        corr += w2t0*s_ltm[c] + w3t0*s_lts[c];
        float w5t0 = g_wcomb[((320+c)*2+0)*128+oc];
        float w5t1 = g_wcomb[((320+c)*2+1)*128+oc];
        float w6t0 = g_wcomb[((384+c)*2+0)*128+oc];
        float w6t1 = g_wcomb[((384+c)*2+1)*128+oc];
        const float* smc = &s_sm[c*24];
        const float* ssc = &s_ss[c*24];
        corr += w5t0*smc[23] + w6t0*ssc[23];
        #pragma unroll
        for (int p = 0; p < 24; p++) {
            int pm = (p + 23) % 24;   // phase of t-1
            tab[p] = fmaf(w5t0, smc[pm], tab[p]);
            tab[p] = fmaf(w5t1, smc[p],  tab[p]);
            tab[p] = fmaf(w6t0, ssc[pm], tab[p]);
            tab[p] = fmaf(w6t1, ssc[p],  tab[p]);
        }
    }
    #pragma unroll
    for (int p = 0; p < 24; p++)
        g_tab[(bn*24 + p)*128 + oc] = tab[p] + base;
    g_corr[bn*128 + oc] = corr;
}

// ---------------- K4: fused gated conv + output 1x1s (f32x2, pipelined) ------
__device__ __forceinline__ float gather_xcat(const float* __restrict__ x,
                                             int b, int ch, int n, int t){
    int g = ch >> 6, c = ch & 63;
    int row = (b*Cc + c)*Nn + n;
    int tc = (t < Tc) ? t : (Tc - 1);
    switch (g) {
        case 0:  return x[row*Tc + tc];
        case 1:  return g_x1[row*TP + t];
        case 4:  return g_x2[row*TP + t];
        case 7:  return g_x3[row*TP + t];
        case 8:  return g_stm[row*Tc + tc];
        case 9:  return g_sts[row*Tc + tc];
        case 10: return g_x4[row*TP + t];
        case 11: return g_spm[row*Tc + tc];
        default: return g_sps[row*Tc + tc];   // 12
    }
}

__device__ __forceinline__ int kt_of(int kti){
    return (kti < 8) ? kti : ((kti < 12) ? kti + 8 : kti + 16);
}

// dynamic smem layout (floats):
//   xs2   [0, 2176)        two buffers of 1088 (16 ic x 68)
//   sw2   [2176, 10368)    two weight buffers of 4096
//   zs    [10368, 14720)   z [64][68]
//   tabs  [14720, 17792)
//   corrs [17792, 17920)
#define KC_XS    0
#define KC_SW    2176
#define KC_ZS    10368
#define KC_TABS  14720
#define KC_CORRS 17792
#define KC_FLOATS 17920
#define KC_BYTES (KC_FLOATS*4)

__global__ void __launch_bounds__(256) k_convout(const float* __restrict__ x,
        const float* __restrict__ c1b, const float* __restrict__ c2b,
        const float* __restrict__ resb, const float* __restrict__ skb,
        float* __restrict__ out){
    extern __shared__ __align__(16) float sm[];
    float* xs2   = sm + KC_XS;
    float* sw2   = sm + KC_SW;
    float* zs    = sm + KC_ZS;
    float* tabs  = sm + KC_TABS;
    float* corrs = sm + KC_CORRS;

    int t0 = blockIdx.x * 64;
    int n  = blockIdx.y;
    int b  = blockIdx.z;
    int bn = b*Nn + n;
    int tid = threadIdx.x;
    for (int idx = tid; idx < 3072; idx += 256) tabs[idx] = g_tab[bn*3072 + idx];
    if (tid < 128) corrs[tid] = g_corr[bn*128 + tid];

    // ---- preload tile kti=0 into buffer 0 ----
    {
        int kt = kt_of(0);
        for (int idx = tid; idx < 1040; idx += 256) {
            int icl = idx / 65, j = idx - icl*65;
            int t = t0 - 1 + j;
            float v = 0.f;
            if (t >= 0 && t < TP) v = gather_xcat(x, b, kt*16 + icl, n, t);
            xs2[icl*68 + j] = v;
        }
        #pragma unroll
        for (int i = 0; i < 4; i++)
            *(float4*)&sw2[i*1024 + tid*4] =
                *(const float4*)&g_wcomb[kt*4096 + i*1024 + tid*4];
    }
    __syncthreads();

    int ocg = tid & 15;   // c base = ocg*4
    int tg  = tid >> 4;   // t base = tg*4
    int tb4 = tg*4;
    ull acc1[2][4] = {}, acc2[2][4] = {};
    int p = 0;
    for (int kti = 0; kti < 36; kti++) {
        // ---- prefetch next tile into registers (overlaps with compute) ----
        float xr[5];
        float4 wr[4];
        bool has_next = (kti + 1 < 36);
        if (has_next) {
            int kt = kt_of(kti + 1);
            #pragma unroll
            for (int k = 0; k < 5; k++) {
                int idx = tid + k*256;
                float v = 0.f;
                if (idx < 1040) {
                    int icl = idx / 65, j = idx - icl*65;
                    int t = t0 - 1 + j;
                    if (t >= 0 && t < TP) v = gather_xcat(x, b, kt*16 + icl, n, t);
                }
                xr[k] = v;
            }
            #pragma unroll
            for (int i = 0; i < 4; i++)
                wr[i] = *(const float4*)&g_wcomb[kt*4096 + i*1024 + tid*4];
        }
        // ---- compute from buffer p ----
        const float* xs = xs2 + p*1088;
        const float* sw = sw2 + p*4096;
        #pragma unroll
        for (int ic = 0; ic < 16; ic++) {
            float4 xv4 = *(const float4*)&xs[ic*68 + tb4];
            float xv5 = xs[ic*68 + tb4 + 4];
            ull xd[5] = {packdup(xv4.x), packdup(xv4.y), packdup(xv4.z),
                         packdup(xv4.w), packdup(xv5)};
            #pragma unroll
            for (int tap = 0; tap < 2; tap++) {
                ulonglong2 wA = *(const ulonglong2*)&sw[(ic*2+tap)*128 + ocg*4];
                ulonglong2 wB = *(const ulonglong2*)&sw[(ic*2+tap)*128 + 64 + ocg*4];
                #pragma unroll
                for (int j = 0; j < 4; j++) {
                    fma2(acc1[0][j], wA.x, xd[j+tap]);
                    fma2(acc1[1][j], wA.y, xd[j+tap]);
                    fma2(acc2[0][j], wB.x, xd[j+tap]);
                    fma2(acc2[1][j], wB.y, xd[j+tap]);
                }
            }
        }
        // ---- store prefetched tile into the other buffer ----
        if (has_next) {
            float* xsn = xs2 + (1-p)*1088;
            float* swn = sw2 + (1-p)*4096;
            #pragma unroll
            for (int k = 0; k < 5; k++) {
                int idx = tid + k*256;
                if (idx < 1040) {
                    int icl = idx / 65, j = idx - icl*65;
                    xsn[icl*68 + j] = xr[k];
                }
            }
            #pragma unroll
            for (int i = 0; i < 4; i++)
                *(float4*)&swn[i*1024 + tid*4] = wr[i];
        }
        __syncthreads();
        p ^= 1;
    }
    // unpack packed accumulators -> f1[i][j], f2[i][j]  (i = oc local 0..3)
    float f1[4][4], f2[4][4];
    #pragma unroll
    for (int ip = 0; ip < 2; ip++)
        #pragma unroll
        for (int j = 0; j < 4; j++) {
            unpack2(acc1[ip][j], f1[ip*2][j], f1[ip*2+1][j]);
            unpack2(acc2[ip][j], f2[ip*2][j], f2[ip*2+1][j]);
        }
    // gating epilogue: z -> zs [c][t_local] stride 68
    #pragma unroll
    for (int i = 0; i < 4; i++) {
        int c = ocg*4 + i;
        float bb1 = c1b[c], bb2 = c2b[c];
        #pragma unroll
        for (int j = 0; j < 4; j++) {
            int lt = tb4 + j;
            int t = t0 + lt;
            int ph = t % 24;
            float a1 = f1[i][j] + tabs[ph*128 + c]      + bb1;
            float a2 = f2[i][j] + tabs[ph*128 + 64 + c] + bb2;
            if (t == 0) { a1 -= corrs[c]; a2 -= corrs[64 + c]; }
            float zg = tanhf(a1) * (1.f / (1.f + expf(-a2)));
            zs[c*68 + lt] = zg;
        }
    }
    __syncthreads();
    // output 1x1 convs on z (f32x2)
    const float* wsel = (t0 + tb4 >= Tc) ? g_wkT : g_wrT;
    ull ao[2][4] = {};
    #pragma unroll 4
    for (int k = 0; k < 64; k++) {
        float4 zv = *(const float4*)&zs[k*68 + tb4];
        ulonglong2 wp = *(const ulonglong2*)&wsel[k*64 + ocg*4];
        ull zd[4] = {packdup(zv.x), packdup(zv.y), packdup(zv.z), packdup(zv.w)};
        #pragma unroll
        for (int j = 0; j < 4; j++) {
            fma2(ao[0][j], wp.x, zd[j]);
            fma2(ao[1][j], wp.y, zd[j]);
        }
    }
    float acc[4][4];
    #pragma unroll
    for (int ip = 0; ip < 2; ip++)
        #pragma unroll
        for (int j = 0; j < 4; j++)
            unpack2(ao[ip][j], acc[ip*2][j], acc[ip*2+1][j]);
    const size_t SZ1 = (size_t)Bc*Cc*Nn*Tc;
    #pragma unroll
    for (int i = 0; i < 4; i++) {
        int oc = ocg*4 + i;
        float br = resb[oc], bk = skb[oc];
        #pragma unroll
        for (int j = 0; j < 4; j++) {
            int t = t0 + tb4 + j;
            if (t < Tc)
                out[((size_t)(b*Cc + oc)*Nn + n)*Tc + t] = acc[i][j] + br;
            else if (t < TP)
                out[SZ1 + ((size_t)(b*Cc + oc)*Nn + n)*PRED + (t - Tc)] = acc[i][j] + bk;
        }
    }
}

// ---------------- launcher ----------------------------------------------------
extern "C" void kernel_launch(void* const* d_in, const int* in_sizes, int n_in,
                              void* d_out, int out_size){
    const float* x    = (const float*)d_in[0];
    const float* emb  = (const float*)d_in[1];
    const float* re1w = (const float*)d_in[2];  const float* re1b = (const float*)d_in[3];
    const float* re2w = (const float*)d_in[4];  const float* re2b = (const float*)d_in[5];
    const float* re3w = (const float*)d_in[6];  const float* re3b = (const float*)d_in[7];
    const float* re4w = (const float*)d_in[8];  const float* re4b = (const float*)d_in[9];
    const float* c1w  = (const float*)d_in[10]; const float* c1b  = (const float*)d_in[11];
    const float* c2w  = (const float*)d_in[12]; const float* c2b  = (const float*)d_in[13];
    const float* skw  = (const float*)d_in[14]; const float* skb  = (const float*)d_in[15];
    const float* resw = (const float*)d_in[16]; const float* resb = (const float*)d_in[17];

    cudaFuncSetAttribute(k_convout, cudaFuncAttributeMaxDynamicSharedMemorySize,
                         KC_BYTES);

    k_adj<<<128, 128>>>(emb);
    k_wprep<<<(832*2*128 + 255)/256, 256>>>(c1w, c2w, resw, skw);
    k_temporal<<<ROWS, Tc>>>(x);
    k_spatial<<<dim3(512, 9, 1), 256>>>();
    k_extrap<<<dim3(12, 4, 32), 256>>>(re1w, re1b, re2w, re2b, re3w, re3b, re4w, re4b);
    k_tab<<<Bc*Nn, 128>>>();
    k_convout<<<dim3(5, 128, 8), 256, KC_BYTES>>>(x, c1b, c2b, resb, skb, (float*)d_out);
}